// round 1
// baseline (speedup 1.0000x reference)
#include <cuda_runtime.h>
#include <math.h>

// Problem dims
#define BB 2
#define SSEQ 2048
#define EE 1024
#define HH 16
#define DD 64
#define MMROWS (BB * SSEQ)  // 4096

// Scratch (device globals: allocation-free)
__device__ float g_Q[BB * HH * SSEQ * DD];
__device__ float g_K[BB * HH * SSEQ * DD];
__device__ float g_V[BB * HH * SSEQ * DD];
__device__ float g_attn[BB * SSEQ * EE];

// ---------------------------------------------------------------------------
// GEMM: C[m,n] = sum_k A[m,k] * W[n,k] + bias[n]
// MODE 0/1/2: write into g_Q/g_K/g_V with [B,H,S,D] scatter
// MODE 3:     A = g_attn, write C row-major to Cout
// ---------------------------------------------------------------------------
#define BM 128
#define BN 128
#define BK 16
#define TM 8
#define TN 8

template <int MODE>
__global__ __launch_bounds__(256) void gemm128(const float* __restrict__ Ain,
                                               const float* __restrict__ W,
                                               const float* __restrict__ bias,
                                               float* __restrict__ Cout) {
    const float* A = (MODE == 3) ? g_attn : Ain;

    __shared__ __align__(16) float As[BK][BM + 4];
    __shared__ __align__(16) float Bs[BK][BN + 4];

    const int tid = threadIdx.x;
    const int n0 = blockIdx.x * BN;
    const int m0 = blockIdx.y * BM;
    const int tx = tid & 15;
    const int ty = tid >> 4;
    const int row = ty * TM;
    const int col = tx * TN;

    float acc[TM][TN];
#pragma unroll
    for (int i = 0; i < TM; i++)
#pragma unroll
        for (int j = 0; j < TN; j++) acc[i][j] = 0.f;

    for (int k0 = 0; k0 < EE; k0 += BK) {
        // Load A tile (128x16) and W tile (128x16), transposed into smem
#pragma unroll
        for (int l = 0; l < 2; l++) {
            int e = tid + l * 256;      // 0..511
            int m = e >> 2;             // 0..127
            int kq = (e & 3) * 4;       // 0,4,8,12
            float4 va = *(const float4*)&A[(size_t)(m0 + m) * EE + k0 + kq];
            As[kq + 0][m] = va.x;
            As[kq + 1][m] = va.y;
            As[kq + 2][m] = va.z;
            As[kq + 3][m] = va.w;
            float4 vw = *(const float4*)&W[(size_t)(n0 + m) * EE + k0 + kq];
            Bs[kq + 0][m] = vw.x;
            Bs[kq + 1][m] = vw.y;
            Bs[kq + 2][m] = vw.z;
            Bs[kq + 3][m] = vw.w;
        }
        __syncthreads();

#pragma unroll
        for (int k = 0; k < BK; ++k) {
            float a[TM], b[TN];
#pragma unroll
            for (int i = 0; i < TM; i += 4) {
                float4 t = *(const float4*)&As[k][row + i];
                a[i] = t.x; a[i + 1] = t.y; a[i + 2] = t.z; a[i + 3] = t.w;
            }
#pragma unroll
            for (int j = 0; j < TN; j += 4) {
                float4 t = *(const float4*)&Bs[k][col + j];
                b[j] = t.x; b[j + 1] = t.y; b[j + 2] = t.z; b[j + 3] = t.w;
            }
#pragma unroll
            for (int i = 0; i < TM; i++)
#pragma unroll
                for (int j = 0; j < TN; j++)
                    acc[i][j] = fmaf(a[i], b[j], acc[i][j]);
        }
        __syncthreads();
    }

    // Epilogue
    if (MODE < 3) {
        float* dst = (MODE == 0) ? g_Q : (MODE == 1) ? g_K : g_V;
#pragma unroll
        for (int i = 0; i < TM; i++) {
            int m = m0 + row + i;
            int bb = m >> 11;        // / SSEQ
            int s = m & (SSEQ - 1);
#pragma unroll
            for (int j = 0; j < TN; j++) {
                int n = n0 + col + j;
                int h = n >> 6;      // / DD
                int d = n & (DD - 1);
                float v = acc[i][j] + bias[n];
                dst[(((size_t)(bb * HH + h)) * SSEQ + s) * DD + d] = v;
            }
        }
    } else {
#pragma unroll
        for (int i = 0; i < TM; i++) {
            int m = m0 + row + i;
#pragma unroll
            for (int j = 0; j < TN; j++) {
                int n = n0 + col + j;
                Cout[(size_t)m * EE + n] = acc[i][j] + bias[n];
            }
        }
    }
}

// ---------------------------------------------------------------------------
// RoPE (interleaved rotate, half-concat angle tables) applied in-place to Q,K
// out[2i]   = x[2i]  *cos(ang(2i))   - x[2i+1]*sin(ang(2i))
// out[2i+1] = x[2i+1]*cos(ang(2i+1)) + x[2i]  *sin(ang(2i+1))
// ang(d) = s * 10000^(-(d mod 32)/32)
// ---------------------------------------------------------------------------
__global__ __launch_bounds__(256) void rope_kernel() {
    const int NH = BB * HH * SSEQ * (DD / 2);
    int idx = blockIdx.x * blockDim.x + threadIdx.x;
    if (idx >= 2 * NH) return;
    float* buf = (idx < NH) ? g_Q : g_K;
    int t = (idx < NH) ? idx : idx - NH;
    int j = t & 31;
    t >>= 5;
    int s = t & (SSEQ - 1);
    t >>= 11;  // t = b*HH + h
    size_t base = ((size_t)t * SSEQ + s) * DD;

    int d0 = 2 * j, d1 = 2 * j + 1;
    float invf0 = (float)exp(-(double)(d0 & 31) / 32.0 * 9.210340371976184);
    float invf1 = (float)exp(-(double)(d1 & 31) / 32.0 * 9.210340371976184);
    float ang0 = (float)s * invf0;
    float ang1 = (float)s * invf1;
    float s0, c0, s1, c1;
    sincosf(ang0, &s0, &c0);
    sincosf(ang1, &s1, &c1);

    float x0 = buf[base + d0];
    float x1 = buf[base + d1];
    buf[base + d0] = x0 * c0 - x1 * s0;
    buf[base + d1] = x1 * c1 + x0 * s1;
}

// ---------------------------------------------------------------------------
// Flash-style attention: one CTA per (b*H, 64 q-rows). fp32.
// ---------------------------------------------------------------------------
#define QT 64
#define KT 64
#define LDP 65  // padded smem stride

__global__ __launch_bounds__(256) void attn_kernel(const int* __restrict__ mask) {
    extern __shared__ float sm[];
    float* Qs = sm;                 // 64*65
    float* KVs = Qs + QT * LDP;     // 64*65 (K then V, reused)
    float* Ss = KVs + KT * LDP;     // 64*65 (scores -> P)
    float* mrow = Ss + QT * LDP;    // 64
    float* lrow = mrow + QT;        // 64
    float* arow = lrow + QT;        // 64
    int* msk = (int*)(arow + QT);   // 64

    const int tid = threadIdx.x;
    const int bh = blockIdx.y;            // b*HH + h
    const int q0 = blockIdx.x * QT;
    const int b = bh / HH;
    const int h = bh - b * HH;
    const size_t base = (size_t)bh * SSEQ * DD;

    // Load Q tile
    for (int e = tid; e < QT * DD; e += 256) {
        int r = e >> 6, d = e & 63;
        Qs[r * LDP + d] = g_Q[base + (size_t)(q0 + r) * DD + d];
    }
    if (tid < QT) {
        mrow[tid] = -INFINITY;
        lrow[tid] = 0.f;
    }
    const int ty = tid >> 4, tx = tid & 15;
    const int r0 = ty * 4, c0 = tx * 4;
    float acc[4][4];
#pragma unroll
    for (int i = 0; i < 4; i++)
#pragma unroll
        for (int j = 0; j < 4; j++) acc[i][j] = 0.f;
    __syncthreads();

    for (int kt = 0; kt < SSEQ / KT; kt++) {
        const int k0 = kt * KT;
        // Load K tile + mask
        for (int e = tid; e < KT * DD; e += 256) {
            int r = e >> 6, d = e & 63;
            KVs[r * LDP + d] = g_K[base + (size_t)(k0 + r) * DD + d];
        }
        if (tid < KT) msk[tid] = mask[b * SSEQ + k0 + tid];
        __syncthreads();

        // Scores: S = Q @ K^T
        float s4[4][4];
#pragma unroll
        for (int i = 0; i < 4; i++)
#pragma unroll
            for (int j = 0; j < 4; j++) s4[i][j] = 0.f;
        for (int d = 0; d < DD; d++) {
            float a0 = Qs[(r0 + 0) * LDP + d];
            float a1 = Qs[(r0 + 1) * LDP + d];
            float a2 = Qs[(r0 + 2) * LDP + d];
            float a3 = Qs[(r0 + 3) * LDP + d];
            float b0 = KVs[(c0 + 0) * LDP + d];
            float b1 = KVs[(c0 + 1) * LDP + d];
            float b2 = KVs[(c0 + 2) * LDP + d];
            float b3 = KVs[(c0 + 3) * LDP + d];
            s4[0][0] = fmaf(a0, b0, s4[0][0]); s4[0][1] = fmaf(a0, b1, s4[0][1]);
            s4[0][2] = fmaf(a0, b2, s4[0][2]); s4[0][3] = fmaf(a0, b3, s4[0][3]);
            s4[1][0] = fmaf(a1, b0, s4[1][0]); s4[1][1] = fmaf(a1, b1, s4[1][1]);
            s4[1][2] = fmaf(a1, b2, s4[1][2]); s4[1][3] = fmaf(a1, b3, s4[1][3]);
            s4[2][0] = fmaf(a2, b0, s4[2][0]); s4[2][1] = fmaf(a2, b1, s4[2][1]);
            s4[2][2] = fmaf(a2, b2, s4[2][2]); s4[2][3] = fmaf(a2, b3, s4[2][3]);
            s4[3][0] = fmaf(a3, b0, s4[3][0]); s4[3][1] = fmaf(a3, b1, s4[3][1]);
            s4[3][2] = fmaf(a3, b2, s4[3][2]); s4[3][3] = fmaf(a3, b3, s4[3][3]);
        }
#pragma unroll
        for (int i = 0; i < 4; i++)
#pragma unroll
            for (int j = 0; j < 4; j++) {
                float v = s4[i][j] * 0.125f;  // 1/sqrt(64)
                if (msk[c0 + j] == 0) v = -1e30f;
                Ss[(r0 + i) * LDP + c0 + j] = v;
            }
        __syncthreads();

        // Load V tile (overwrites K) — overlapped with softmax below
        for (int e = tid; e < KT * DD; e += 256) {
            int r = e >> 6, d = e & 63;
            KVs[r * LDP + d] = g_V[base + (size_t)(k0 + r) * DD + d];
        }
        // Online softmax, one thread per q-row
        if (tid < QT) {
            int t = tid;
            float mold = mrow[t];
            float mloc = mold;
            for (int jj = 0; jj < KT; jj++) mloc = fmaxf(mloc, Ss[t * LDP + jj]);
            float a = (mold == -INFINITY) ? 0.f : __expf(mold - mloc);
            float ls = 0.f;
            for (int jj = 0; jj < KT; jj++) {
                float p = __expf(Ss[t * LDP + jj] - mloc);
                Ss[t * LDP + jj] = p;
                ls += p;
            }
            mrow[t] = mloc;
            lrow[t] = lrow[t] * a + ls;
            arow[t] = a;
        }
        __syncthreads();

        // Rescale accumulators, then O += P @ V
        float al0 = arow[r0 + 0], al1 = arow[r0 + 1], al2 = arow[r0 + 2], al3 = arow[r0 + 3];
#pragma unroll
        for (int j = 0; j < 4; j++) {
            acc[0][j] *= al0; acc[1][j] *= al1; acc[2][j] *= al2; acc[3][j] *= al3;
        }
        for (int jj = 0; jj < KT; jj++) {
            float p0 = Ss[(r0 + 0) * LDP + jj];
            float p1 = Ss[(r0 + 1) * LDP + jj];
            float p2 = Ss[(r0 + 2) * LDP + jj];
            float p3 = Ss[(r0 + 3) * LDP + jj];
            float v0 = KVs[jj * LDP + c0 + 0];
            float v1 = KVs[jj * LDP + c0 + 1];
            float v2 = KVs[jj * LDP + c0 + 2];
            float v3 = KVs[jj * LDP + c0 + 3];
            acc[0][0] = fmaf(p0, v0, acc[0][0]); acc[0][1] = fmaf(p0, v1, acc[0][1]);
            acc[0][2] = fmaf(p0, v2, acc[0][2]); acc[0][3] = fmaf(p0, v3, acc[0][3]);
            acc[1][0] = fmaf(p1, v0, acc[1][0]); acc[1][1] = fmaf(p1, v1, acc[1][1]);
            acc[1][2] = fmaf(p1, v2, acc[1][2]); acc[1][3] = fmaf(p1, v3, acc[1][3]);
            acc[2][0] = fmaf(p2, v0, acc[2][0]); acc[2][1] = fmaf(p2, v1, acc[2][1]);
            acc[2][2] = fmaf(p2, v2, acc[2][2]); acc[2][3] = fmaf(p2, v3, acc[2][3]);
            acc[3][0] = fmaf(p3, v0, acc[3][0]); acc[3][1] = fmaf(p3, v1, acc[3][1]);
            acc[3][2] = fmaf(p3, v2, acc[3][2]); acc[3][3] = fmaf(p3, v3, acc[3][3]);
        }
        __syncthreads();
    }

    // Epilogue: normalize, write to g_attn in [B,S,H*D] layout
    float inv0 = 1.f / lrow[r0 + 0];
    float inv1 = 1.f / lrow[r0 + 1];
    float inv2 = 1.f / lrow[r0 + 2];
    float inv3 = 1.f / lrow[r0 + 3];
#pragma unroll
    for (int j = 0; j < 4; j++) {
        size_t col = (size_t)h * DD + c0 + j;
        g_attn[((size_t)b * SSEQ + q0 + r0 + 0) * EE + col] = acc[0][j] * inv0;
        g_attn[((size_t)b * SSEQ + q0 + r0 + 1) * EE + col] = acc[1][j] * inv1;
        g_attn[((size_t)b * SSEQ + q0 + r0 + 2) * EE + col] = acc[2][j] * inv2;
        g_attn[((size_t)b * SSEQ + q0 + r0 + 3) * EE + col] = acc[3][j] * inv3;
    }
}

// ---------------------------------------------------------------------------
extern "C" void kernel_launch(void* const* d_in, const int* in_sizes, int n_in,
                              void* d_out, int out_size) {
    const float* query = (const float*)d_in[0];
    const float* key   = (const float*)d_in[1];
    const float* value = (const float*)d_in[2];
    const int*   mask  = (const int*)d_in[3];
    const float* Wq = (const float*)d_in[4];
    const float* bq = (const float*)d_in[5];
    const float* Wk = (const float*)d_in[6];
    const float* bk = (const float*)d_in[7];
    const float* Wv = (const float*)d_in[8];
    const float* bv = (const float*)d_in[9];
    const float* Wo = (const float*)d_in[10];
    const float* bo = (const float*)d_in[11];
    float* out = (float*)d_out;

    dim3 gemm_grid(EE / BN, MMROWS / BM);  // (8, 32)

    gemm128<0><<<gemm_grid, 256>>>(query, Wq, bq, nullptr);
    gemm128<1><<<gemm_grid, 256>>>(key, Wk, bk, nullptr);
    gemm128<2><<<gemm_grid, 256>>>(value, Wv, bv, nullptr);

    const int NH2 = 2 * BB * HH * SSEQ * (DD / 2);
    rope_kernel<<<(NH2 + 255) / 256, 256>>>();

    const int smem = (3 * QT * LDP + 3 * QT) * (int)sizeof(float) + QT * (int)sizeof(int);
    static bool attr_set = false;
    if (!attr_set) {
        cudaFuncSetAttribute(attn_kernel, cudaFuncAttributeMaxDynamicSharedMemorySize, smem);
        attr_set = true;
    }
    attn_kernel<<<dim3(SSEQ / QT, BB * HH), 256, smem>>>(mask);

    gemm128<3><<<gemm_grid, 256>>>(nullptr, Wo, bo, out);
}

// round 2
// speedup vs baseline: 1.1525x; 1.1525x over previous
#include <cuda_runtime.h>
#include <math.h>

// Problem dims
#define BB 2
#define SSEQ 2048
#define EE 1024
#define HH 16
#define DD 64
#define MMROWS (BB * SSEQ)  // 4096

// Scratch (device globals: allocation-free)
__device__ float g_Q[BB * HH * SSEQ * DD];
__device__ float g_K[BB * HH * SSEQ * DD];
__device__ float g_V[BB * HH * SSEQ * DD];
__device__ float g_attn[BB * SSEQ * EE];

// ---------------------------------------------------------------------------
// GEMM: C[m,n] = sum_k A[m,k] * W[n,k] + bias[n]
// MODE 0/1/2: write into g_Q/g_K/g_V with [B,H,S,D] scatter
// MODE 3:     A = g_attn, write C row-major to Cout
// ---------------------------------------------------------------------------
#define BM 128
#define BN 128
#define BK 16
#define TM 8
#define TN 8

template <int MODE>
__global__ __launch_bounds__(256) void gemm128(const float* __restrict__ Ain,
                                               const float* __restrict__ W,
                                               const float* __restrict__ bias,
                                               float* __restrict__ Cout) {
    const float* A = (MODE == 3) ? g_attn : Ain;

    __shared__ __align__(16) float As[BK][BM + 4];
    __shared__ __align__(16) float Bs[BK][BN + 4];

    const int tid = threadIdx.x;
    const int n0 = blockIdx.x * BN;
    const int m0 = blockIdx.y * BM;
    const int tx = tid & 15;
    const int ty = tid >> 4;
    const int row = ty * TM;
    const int col = tx * TN;

    float acc[TM][TN];
#pragma unroll
    for (int i = 0; i < TM; i++)
#pragma unroll
        for (int j = 0; j < TN; j++) acc[i][j] = 0.f;

    for (int k0 = 0; k0 < EE; k0 += BK) {
        // Load A tile (128x16) and W tile (128x16), transposed into smem
#pragma unroll
        for (int l = 0; l < 2; l++) {
            int e = tid + l * 256;      // 0..511
            int m = e >> 2;             // 0..127
            int kq = (e & 3) * 4;       // 0,4,8,12
            float4 va = *(const float4*)&A[(size_t)(m0 + m) * EE + k0 + kq];
            As[kq + 0][m] = va.x;
            As[kq + 1][m] = va.y;
            As[kq + 2][m] = va.z;
            As[kq + 3][m] = va.w;
            float4 vw = *(const float4*)&W[(size_t)(n0 + m) * EE + k0 + kq];
            Bs[kq + 0][m] = vw.x;
            Bs[kq + 1][m] = vw.y;
            Bs[kq + 2][m] = vw.z;
            Bs[kq + 3][m] = vw.w;
        }
        __syncthreads();

#pragma unroll
        for (int k = 0; k < BK; ++k) {
            float a[TM], b[TN];
#pragma unroll
            for (int i = 0; i < TM; i += 4) {
                float4 t = *(const float4*)&As[k][row + i];
                a[i] = t.x; a[i + 1] = t.y; a[i + 2] = t.z; a[i + 3] = t.w;
            }
#pragma unroll
            for (int j = 0; j < TN; j += 4) {
                float4 t = *(const float4*)&Bs[k][col + j];
                b[j] = t.x; b[j + 1] = t.y; b[j + 2] = t.z; b[j + 3] = t.w;
            }
#pragma unroll
            for (int i = 0; i < TM; i++)
#pragma unroll
                for (int j = 0; j < TN; j++)
                    acc[i][j] = fmaf(a[i], b[j], acc[i][j]);
        }
        __syncthreads();
    }

    // Epilogue
    if (MODE < 3) {
        float* dst = (MODE == 0) ? g_Q : (MODE == 1) ? g_K : g_V;
#pragma unroll
        for (int i = 0; i < TM; i++) {
            int m = m0 + row + i;
            int bb = m >> 11;        // / SSEQ
            int s = m & (SSEQ - 1);
#pragma unroll
            for (int j = 0; j < TN; j++) {
                int n = n0 + col + j;
                int h = n >> 6;      // / DD
                int d = n & (DD - 1);
                float v = acc[i][j] + bias[n];
                dst[(((size_t)(bb * HH + h)) * SSEQ + s) * DD + d] = v;
            }
        }
    } else {
#pragma unroll
        for (int i = 0; i < TM; i++) {
            int m = m0 + row + i;
#pragma unroll
            for (int j = 0; j < TN; j++) {
                int n = n0 + col + j;
                Cout[(size_t)m * EE + n] = acc[i][j] + bias[n];
            }
        }
    }
}

// ---------------------------------------------------------------------------
// RoPE v2: per-block inv_freq table (double exp once), float2 per thread.
// pair idx -> elements (2p, 2p+1) of row s of head bh.
// out[2p]   = x[2p]  *cos(ang(2p))   - x[2p+1]*sin(ang(2p))
// out[2p+1] = x[2p+1]*cos(ang(2p+1)) + x[2p]  *sin(ang(2p+1))
// ang(d) = s * 10000^(-(d mod 32)/32)
// ---------------------------------------------------------------------------
__global__ __launch_bounds__(256) void rope_kernel2() {
    __shared__ float invf[32];
    if (threadIdx.x < 32)
        invf[threadIdx.x] = (float)exp(-(double)threadIdx.x * (9.210340371976184 / 32.0));
    __syncthreads();

    const int NPAIR = BB * HH * SSEQ * 32;  // per tensor
    int idx = blockIdx.x * blockDim.x + threadIdx.x;
    if (idx >= 2 * NPAIR) return;
    float* buf = (idx < NPAIR) ? g_Q : g_K;
    int t = (idx < NPAIR) ? idx : idx - NPAIR;
    int p = t & 31;            // pair index within head dim
    int s = (t >> 5) & (SSEQ - 1);

    int d0 = 2 * p, d1 = 2 * p + 1;
    float ang0 = (float)s * invf[d0 & 31];
    float ang1 = (float)s * invf[d1 & 31];
    float s0, c0, s1, c1;
    sincosf(ang0, &s0, &c0);
    sincosf(ang1, &s1, &c1);

    float2* ptr = (float2*)buf + t;   // elements 2t, 2t+1 are contiguous
    float2 x = *ptr;
    float2 y;
    y.x = x.x * c0 - x.y * s0;
    y.y = x.y * c1 + x.x * s1;
    *ptr = y;
}

// ---------------------------------------------------------------------------
// Flash-style attention: one CTA per (b*H, 64 q-rows). fp32.
// Register-resident online softmax with shfl reductions.
// ---------------------------------------------------------------------------
#define QT 64
#define KT 64
#define LDP 65  // padded smem stride

__global__ __launch_bounds__(256) void attn_kernel(const int* __restrict__ mask) {
    extern __shared__ float sm[];
    float* Qs = sm;                 // 64*65
    float* KVs = Qs + QT * LDP;     // 64*65 (K then V, reused)
    float* Ss = KVs + KT * LDP;     // 64*65 (P tile)
    int* msk = (int*)(Ss + QT * LDP);  // 64

    const int tid = threadIdx.x;
    const int bh = blockIdx.y;            // b*HH + h
    const int q0 = blockIdx.x * QT;
    const int b = bh / HH;
    const int h = bh - b * HH;
    const size_t base = (size_t)bh * SSEQ * DD;

    // Load Q tile (float4 gmem reads, scalar padded smem stores)
    for (int e = tid; e < QT * DD / 4; e += 256) {
        int r = e >> 4;            // 16 float4 per 64-wide row
        int d = (e & 15) * 4;
        float4 v = *(const float4*)&g_Q[base + (size_t)(q0 + r) * DD + d];
        Qs[r * LDP + d + 0] = v.x;
        Qs[r * LDP + d + 1] = v.y;
        Qs[r * LDP + d + 2] = v.z;
        Qs[r * LDP + d + 3] = v.w;
    }

    const int ty = tid >> 4, tx = tid & 15;
    const int r0 = ty * 4, c0 = tx * 4;
    float acc[4][4];
    float mr[4], lr[4];
#pragma unroll
    for (int i = 0; i < 4; i++) {
        mr[i] = -INFINITY;
        lr[i] = 0.f;
#pragma unroll
        for (int j = 0; j < 4; j++) acc[i][j] = 0.f;
    }
    __syncthreads();

    for (int kt = 0; kt < SSEQ / KT; kt++) {
        const int k0 = kt * KT;
        // Load K tile + mask
        for (int e = tid; e < KT * DD / 4; e += 256) {
            int r = e >> 4;
            int d = (e & 15) * 4;
            float4 v = *(const float4*)&g_K[base + (size_t)(k0 + r) * DD + d];
            KVs[r * LDP + d + 0] = v.x;
            KVs[r * LDP + d + 1] = v.y;
            KVs[r * LDP + d + 2] = v.z;
            KVs[r * LDP + d + 3] = v.w;
        }
        if (tid < KT) msk[tid] = mask[b * SSEQ + k0 + tid];
        __syncthreads();

        // Scores: S = Q @ K^T (4x4 fragment per thread)
        float s4[4][4];
#pragma unroll
        for (int i = 0; i < 4; i++)
#pragma unroll
            for (int j = 0; j < 4; j++) s4[i][j] = 0.f;
        for (int d = 0; d < DD; d++) {
            float a0 = Qs[(r0 + 0) * LDP + d];
            float a1 = Qs[(r0 + 1) * LDP + d];
            float a2 = Qs[(r0 + 2) * LDP + d];
            float a3 = Qs[(r0 + 3) * LDP + d];
            float b0 = KVs[(c0 + 0) * LDP + d];
            float b1 = KVs[(c0 + 1) * LDP + d];
            float b2 = KVs[(c0 + 2) * LDP + d];
            float b3 = KVs[(c0 + 3) * LDP + d];
            s4[0][0] = fmaf(a0, b0, s4[0][0]); s4[0][1] = fmaf(a0, b1, s4[0][1]);
            s4[0][2] = fmaf(a0, b2, s4[0][2]); s4[0][3] = fmaf(a0, b3, s4[0][3]);
            s4[1][0] = fmaf(a1, b0, s4[1][0]); s4[1][1] = fmaf(a1, b1, s4[1][1]);
            s4[1][2] = fmaf(a1, b2, s4[1][2]); s4[1][3] = fmaf(a1, b3, s4[1][3]);
            s4[2][0] = fmaf(a2, b0, s4[2][0]); s4[2][1] = fmaf(a2, b1, s4[2][1]);
            s4[2][2] = fmaf(a2, b2, s4[2][2]); s4[2][3] = fmaf(a2, b3, s4[2][3]);
            s4[3][0] = fmaf(a3, b0, s4[3][0]); s4[3][1] = fmaf(a3, b1, s4[3][1]);
            s4[3][2] = fmaf(a3, b2, s4[3][2]); s4[3][3] = fmaf(a3, b3, s4[3][3]);
        }
        // scale + mask in registers
        int mk0 = msk[c0 + 0], mk1 = msk[c0 + 1], mk2 = msk[c0 + 2], mk3 = msk[c0 + 3];
#pragma unroll
        for (int i = 0; i < 4; i++) {
            s4[i][0] = (mk0 == 0) ? -1e30f : s4[i][0] * 0.125f;
            s4[i][1] = (mk1 == 0) ? -1e30f : s4[i][1] * 0.125f;
            s4[i][2] = (mk2 == 0) ? -1e30f : s4[i][2] * 0.125f;
            s4[i][3] = (mk3 == 0) ? -1e30f : s4[i][3] * 0.125f;
        }

        // Online softmax in registers, reduced over the 16-lane tx-group
        float arow[4];
#pragma unroll
        for (int i = 0; i < 4; i++) {
            float tm = fmaxf(fmaxf(s4[i][0], s4[i][1]), fmaxf(s4[i][2], s4[i][3]));
#pragma unroll
            for (int off = 8; off >= 1; off >>= 1)
                tm = fmaxf(tm, __shfl_xor_sync(0xffffffffu, tm, off));
            float mnew = fmaxf(mr[i], tm);
            float a = __expf(mr[i] - mnew);   // 0 on first tile (-inf - finite)
            float ls = 0.f;
#pragma unroll
            for (int j = 0; j < 4; j++) {
                float p = __expf(s4[i][j] - mnew);
                s4[i][j] = p;
                ls += p;
            }
#pragma unroll
            for (int off = 8; off >= 1; off >>= 1)
                ls += __shfl_xor_sync(0xffffffffu, ls, off);
            mr[i] = mnew;
            lr[i] = lr[i] * a + ls;
            arow[i] = a;
            // rescale accumulator
#pragma unroll
            for (int j = 0; j < 4; j++) acc[i][j] *= a;
        }
        (void)arow;
        // write P to smem for PV stage
#pragma unroll
        for (int i = 0; i < 4; i++)
#pragma unroll
            for (int j = 0; j < 4; j++)
                Ss[(r0 + i) * LDP + c0 + j] = s4[i][j];
        __syncthreads();   // all K reads done + P visible

        // Load V tile (overwrites K)
        for (int e = tid; e < KT * DD / 4; e += 256) {
            int r = e >> 4;
            int d = (e & 15) * 4;
            float4 v = *(const float4*)&g_V[base + (size_t)(k0 + r) * DD + d];
            KVs[r * LDP + d + 0] = v.x;
            KVs[r * LDP + d + 1] = v.y;
            KVs[r * LDP + d + 2] = v.z;
            KVs[r * LDP + d + 3] = v.w;
        }
        __syncthreads();

        // O += P @ V
        for (int jj = 0; jj < KT; jj++) {
            float p0 = Ss[(r0 + 0) * LDP + jj];
            float p1 = Ss[(r0 + 1) * LDP + jj];
            float p2 = Ss[(r0 + 2) * LDP + jj];
            float p3 = Ss[(r0 + 3) * LDP + jj];
            float v0 = KVs[jj * LDP + c0 + 0];
            float v1 = KVs[jj * LDP + c0 + 1];
            float v2 = KVs[jj * LDP + c0 + 2];
            float v3 = KVs[jj * LDP + c0 + 3];
            acc[0][0] = fmaf(p0, v0, acc[0][0]); acc[0][1] = fmaf(p0, v1, acc[0][1]);
            acc[0][2] = fmaf(p0, v2, acc[0][2]); acc[0][3] = fmaf(p0, v3, acc[0][3]);
            acc[1][0] = fmaf(p1, v0, acc[1][0]); acc[1][1] = fmaf(p1, v1, acc[1][1]);
            acc[1][2] = fmaf(p1, v2, acc[1][2]); acc[1][3] = fmaf(p1, v3, acc[1][3]);
            acc[2][0] = fmaf(p2, v0, acc[2][0]); acc[2][1] = fmaf(p2, v1, acc[2][1]);
            acc[2][2] = fmaf(p2, v2, acc[2][2]); acc[2][3] = fmaf(p2, v3, acc[2][3]);
            acc[3][0] = fmaf(p3, v0, acc[3][0]); acc[3][1] = fmaf(p3, v1, acc[3][1]);
            acc[3][2] = fmaf(p3, v2, acc[3][2]); acc[3][3] = fmaf(p3, v3, acc[3][3]);
        }
        __syncthreads();
    }

    // Epilogue: normalize, write to g_attn in [B,S,H*D] layout
#pragma unroll
    for (int i = 0; i < 4; i++) {
        float inv = 1.f / lr[i];
#pragma unroll
        for (int j = 0; j < 4; j++) {
            size_t col = (size_t)h * DD + c0 + j;
            g_attn[((size_t)b * SSEQ + q0 + r0 + i) * EE + col] = acc[i][j] * inv;
        }
    }
}

// ---------------------------------------------------------------------------
extern "C" void kernel_launch(void* const* d_in, const int* in_sizes, int n_in,
                              void* d_out, int out_size) {
    const float* query = (const float*)d_in[0];
    const float* key   = (const float*)d_in[1];
    const float* value = (const float*)d_in[2];
    const int*   mask  = (const int*)d_in[3];
    const float* Wq = (const float*)d_in[4];
    const float* bq = (const float*)d_in[5];
    const float* Wk = (const float*)d_in[6];
    const float* bk = (const float*)d_in[7];
    const float* Wv = (const float*)d_in[8];
    const float* bv = (const float*)d_in[9];
    const float* Wo = (const float*)d_in[10];
    const float* bo = (const float*)d_in[11];
    float* out = (float*)d_out;

    dim3 gemm_grid(EE / BN, MMROWS / BM);  // (8, 32)

    gemm128<0><<<gemm_grid, 256>>>(query, Wq, bq, nullptr);
    gemm128<1><<<gemm_grid, 256>>>(key, Wk, bk, nullptr);
    gemm128<2><<<gemm_grid, 256>>>(value, Wv, bv, nullptr);

    const int NPAIR2 = 2 * BB * HH * SSEQ * 32;
    rope_kernel2<<<(NPAIR2 + 255) / 256, 256>>>();

    const int smem = 3 * QT * LDP * (int)sizeof(float) + QT * (int)sizeof(int);
    static bool attr_set = false;
    if (!attr_set) {
        cudaFuncSetAttribute(attn_kernel, cudaFuncAttributeMaxDynamicSharedMemorySize, smem);
        attr_set = true;
    }
    attn_kernel<<<dim3(SSEQ / QT, BB * HH), 256, smem>>>(mask);

    gemm128<3><<<gemm_grid, 256>>>(nullptr, Wo, bo, out);
}

// round 3
// speedup vs baseline: 2.8312x; 2.4565x over previous
#include <cuda_runtime.h>
#include <math.h>
#include <stdint.h>

// Problem dims
#define BB 2
#define SSEQ 2048
#define EE 1024
#define HH 16
#define DD 64
#define MMROWS (BB * SSEQ)  // 4096

// Scratch (device globals: allocation-free)
__device__ float g_Q[BB * HH * SSEQ * DD];
__device__ float g_K[BB * HH * SSEQ * DD];
__device__ float g_V[BB * HH * SSEQ * DD];
__device__ float g_attn[BB * SSEQ * EE];

// ---------------------------------------------------------------------------
// tf32 helpers
// ---------------------------------------------------------------------------
__device__ __forceinline__ float f2tf(float x) {
    uint32_t r;
    asm("cvt.rna.tf32.f32 %0, %1;" : "=r"(r) : "f"(x));
    return __uint_as_float(r);
}

__device__ __forceinline__ void mma_tf32(float& c0, float& c1, float& c2, float& c3,
                                         uint32_t a0, uint32_t a1, uint32_t a2, uint32_t a3,
                                         uint32_t b0, uint32_t b1) {
    asm volatile(
        "mma.sync.aligned.m16n8k8.row.col.f32.tf32.tf32.f32 "
        "{%0,%1,%2,%3}, {%4,%5,%6,%7}, {%8,%9}, {%0,%1,%2,%3};\n"
        : "+f"(c0), "+f"(c1), "+f"(c2), "+f"(c3)
        : "r"(a0), "r"(a1), "r"(a2), "r"(a3), "r"(b0), "r"(b1));
}

// ---------------------------------------------------------------------------
// tf32 tensor-core GEMM: C[m,n] = sum_k A[m,k] * W[n,k] + bias[n]
// MODE 0/1/2: write into g_Q/g_K/g_V with [B,H,S,D] scatter; MODE 3: row-major out.
// 256 thr = 8 warps (2 m x 4 n), warp tile 64x32, CTA tile 128x128, BK=16.
// smem layout [k][m] / [k][n], stride 132 (fragment LDS conflict-free).
// ---------------------------------------------------------------------------
#define GLD 132

template <int MODE>
__global__ __launch_bounds__(256) void gemm_tc(const float* __restrict__ Ain,
                                               const float* __restrict__ W,
                                               const float* __restrict__ bias,
                                               float* __restrict__ Cout) {
    const float* A = (MODE == 3) ? g_attn : Ain;

    __shared__ __align__(16) float As[16][GLD];
    __shared__ __align__(16) float Bs[16][GLD];

    const int tid = threadIdx.x;
    const int n0 = blockIdx.x * 128;
    const int m0 = blockIdx.y * 128;
    const int wid = tid >> 5;
    const int lane = tid & 31;
    const int g = lane >> 2;   // groupID
    const int t4 = lane & 3;   // threadID_in_group
    const int mw = (wid & 1) * 64;
    const int nw = (wid >> 1) * 32;

    float acc[4][4][4];
#pragma unroll
    for (int mt = 0; mt < 4; mt++)
#pragma unroll
        for (int nt = 0; nt < 4; nt++)
#pragma unroll
            for (int q = 0; q < 4; q++) acc[mt][nt][q] = 0.f;

    for (int k0 = 0; k0 < EE; k0 += 16) {
        // Load A tile (128x16) and W tile (128x16), transposed + tf32-rounded
#pragma unroll
        for (int l = 0; l < 2; l++) {
            int e = tid + l * 256;      // 0..511
            int m = e >> 2;             // 0..127
            int kq = (e & 3) * 4;       // 0,4,8,12
            float4 va = *(const float4*)&A[(size_t)(m0 + m) * EE + k0 + kq];
            As[kq + 0][m] = f2tf(va.x);
            As[kq + 1][m] = f2tf(va.y);
            As[kq + 2][m] = f2tf(va.z);
            As[kq + 3][m] = f2tf(va.w);
            float4 vw = *(const float4*)&W[(size_t)(n0 + m) * EE + k0 + kq];
            Bs[kq + 0][m] = f2tf(vw.x);
            Bs[kq + 1][m] = f2tf(vw.y);
            Bs[kq + 2][m] = f2tf(vw.z);
            Bs[kq + 3][m] = f2tf(vw.w);
        }
        __syncthreads();

#pragma unroll
        for (int kk = 0; kk < 16; kk += 8) {
            uint32_t af[4][4];
#pragma unroll
            for (int mt = 0; mt < 4; mt++) {
                int m = mw + mt * 16 + g;
                af[mt][0] = __float_as_uint(As[kk + t4][m]);
                af[mt][1] = __float_as_uint(As[kk + t4][m + 8]);
                af[mt][2] = __float_as_uint(As[kk + t4 + 4][m]);
                af[mt][3] = __float_as_uint(As[kk + t4 + 4][m + 8]);
            }
            uint32_t bf[4][2];
#pragma unroll
            for (int nt = 0; nt < 4; nt++) {
                int n = nw + nt * 8 + g;
                bf[nt][0] = __float_as_uint(Bs[kk + t4][n]);
                bf[nt][1] = __float_as_uint(Bs[kk + t4 + 4][n]);
            }
#pragma unroll
            for (int mt = 0; mt < 4; mt++)
#pragma unroll
                for (int nt = 0; nt < 4; nt++)
                    mma_tf32(acc[mt][nt][0], acc[mt][nt][1], acc[mt][nt][2], acc[mt][nt][3],
                             af[mt][0], af[mt][1], af[mt][2], af[mt][3],
                             bf[nt][0], bf[nt][1]);
        }
        __syncthreads();
    }

    // Epilogue. C frag: c0=(r,c), c1=(r,c+1), c2=(r+8,c), c3=(r+8,c+1)
    // with r = mw+mt*16+g, c = nw+nt*8+2*t4 (c even -> float2 stores OK).
#pragma unroll
    for (int mt = 0; mt < 4; mt++) {
        int gm0 = m0 + mw + mt * 16 + g;
        int gm1 = gm0 + 8;
#pragma unroll
        for (int nt = 0; nt < 4; nt++) {
            int gn = n0 + nw + nt * 8 + 2 * t4;
            float bv0 = bias[gn], bv1 = bias[gn + 1];
            float2 v0 = make_float2(acc[mt][nt][0] + bv0, acc[mt][nt][1] + bv1);
            float2 v1 = make_float2(acc[mt][nt][2] + bv0, acc[mt][nt][3] + bv1);
            if (MODE < 3) {
                float* dst = (MODE == 0) ? g_Q : (MODE == 1) ? g_K : g_V;
                int h = gn >> 6, d = gn & 63;
                {
                    int bb = gm0 >> 11, s = gm0 & (SSEQ - 1);
                    *(float2*)&dst[(((size_t)(bb * HH + h)) * SSEQ + s) * DD + d] = v0;
                }
                {
                    int bb = gm1 >> 11, s = gm1 & (SSEQ - 1);
                    *(float2*)&dst[(((size_t)(bb * HH + h)) * SSEQ + s) * DD + d] = v1;
                }
            } else {
                *(float2*)&Cout[(size_t)gm0 * EE + gn] = v0;
                *(float2*)&Cout[(size_t)gm1 * EE + gn] = v1;
            }
        }
    }
}

// ---------------------------------------------------------------------------
// RoPE v2 (unchanged; 28us, fine)
// ---------------------------------------------------------------------------
__global__ __launch_bounds__(256) void rope_kernel2() {
    __shared__ float invf[32];
    if (threadIdx.x < 32)
        invf[threadIdx.x] = (float)exp(-(double)threadIdx.x * (9.210340371976184 / 32.0));
    __syncthreads();

    const int NPAIR = BB * HH * SSEQ * 32;  // per tensor
    int idx = blockIdx.x * blockDim.x + threadIdx.x;
    if (idx >= 2 * NPAIR) return;
    float* buf = (idx < NPAIR) ? g_Q : g_K;
    int t = (idx < NPAIR) ? idx : idx - NPAIR;
    int p = t & 31;
    int s = (t >> 5) & (SSEQ - 1);

    float ang0 = (float)s * invf[(2 * p) & 31];
    float ang1 = (float)s * invf[(2 * p + 1) & 31];
    float s0, c0, s1, c1;
    sincosf(ang0, &s0, &c0);
    sincosf(ang1, &s1, &c1);

    float2* ptr = (float2*)buf + t;
    float2 x = *ptr;
    float2 y;
    y.x = x.x * c0 - x.y * s0;
    y.y = x.y * c1 + x.x * s1;
    *ptr = y;
}

// ---------------------------------------------------------------------------
// Flash attention with tf32 mma. CTA = 128 thr (4 warps), Q tile 64 (16/warp),
// K tile 64. smem row-major tiles, stride 68 -> all fragment LDS conflict-free.
// ---------------------------------------------------------------------------
#define ALD 68

__global__ __launch_bounds__(128) void attn_tc(const int* __restrict__ mask) {
    extern __shared__ float sm[];
    float* Qs = sm;                  // [64][68] tf32 bits
    float* Ks = Qs + 64 * ALD;       // K tile, then V tile (reused) [64][68]
    float* Ss = Ks + 64 * ALD;       // P tile [64][68] tf32 bits
    int* msk = (int*)(Ss + 64 * ALD);  // 64

    const int tid = threadIdx.x;
    const int wid = tid >> 5;
    const int lane = tid & 31;
    const int g = lane >> 2;
    const int t4 = lane & 3;
    const int qw = wid * 16;          // warp's q-row base (CTA-local)

    const int bh = blockIdx.y;        // b*HH + h
    const int q0 = blockIdx.x * 64;
    const int b = bh / HH;
    const int h = bh - b * HH;
    const size_t base = (size_t)bh * SSEQ * DD;

    // Load Q tile (row-major, tf32-rounded)
    for (int e = tid; e < 64 * DD / 4; e += 128) {
        int r = e >> 4;
        int d = (e & 15) * 4;
        float4 v = *(const float4*)&g_Q[base + (size_t)(q0 + r) * DD + d];
        float4 w = make_float4(f2tf(v.x), f2tf(v.y), f2tf(v.z), f2tf(v.w));
        *(float4*)&Qs[r * ALD + d] = w;
    }

    float o[8][4];
#pragma unroll
    for (int nt = 0; nt < 8; nt++)
#pragma unroll
        for (int q = 0; q < 4; q++) o[nt][q] = 0.f;
    float mr0 = -INFINITY, mr1 = -INFINITY, lr0 = 0.f, lr1 = 0.f;
    __syncthreads();

    for (int kt = 0; kt < SSEQ / 64; kt++) {
        const int k0 = kt * 64;
        // Load K tile (row-major [n][d]) + mask
        for (int e = tid; e < 64 * DD / 4; e += 128) {
            int r = e >> 4;
            int d = (e & 15) * 4;
            float4 v = *(const float4*)&g_K[base + (size_t)(k0 + r) * DD + d];
            float4 w = make_float4(f2tf(v.x), f2tf(v.y), f2tf(v.z), f2tf(v.w));
            *(float4*)&Ks[r * ALD + d] = w;
        }
        if (tid < 64) msk[tid] = mask[b * SSEQ + k0 + tid];
        __syncthreads();

        // S = Q @ K^T : 8 n-tiles of n8, 8 k-steps of k8
        float s[8][4];
#pragma unroll
        for (int nt = 0; nt < 8; nt++)
#pragma unroll
            for (int q = 0; q < 4; q++) s[nt][q] = 0.f;
#pragma unroll
        for (int kk = 0; kk < 64; kk += 8) {
            uint32_t a0 = __float_as_uint(Qs[(qw + g) * ALD + kk + t4]);
            uint32_t a1 = __float_as_uint(Qs[(qw + g + 8) * ALD + kk + t4]);
            uint32_t a2 = __float_as_uint(Qs[(qw + g) * ALD + kk + t4 + 4]);
            uint32_t a3 = __float_as_uint(Qs[(qw + g + 8) * ALD + kk + t4 + 4]);
#pragma unroll
            for (int nt = 0; nt < 8; nt++) {
                uint32_t b0 = __float_as_uint(Ks[(nt * 8 + g) * ALD + kk + t4]);
                uint32_t b1 = __float_as_uint(Ks[(nt * 8 + g) * ALD + kk + t4 + 4]);
                mma_tf32(s[nt][0], s[nt][1], s[nt][2], s[nt][3], a0, a1, a2, a3, b0, b1);
            }
        }

        // scale + mask (frag rows: g, g+8; cols: nt*8 + 2*t4, +1)
#pragma unroll
        for (int nt = 0; nt < 8; nt++) {
            int mka = msk[nt * 8 + 2 * t4];
            int mkb = msk[nt * 8 + 2 * t4 + 1];
            s[nt][0] = mka ? s[nt][0] * 0.125f : -1e30f;
            s[nt][1] = mkb ? s[nt][1] * 0.125f : -1e30f;
            s[nt][2] = mka ? s[nt][2] * 0.125f : -1e30f;
            s[nt][3] = mkb ? s[nt][3] * 0.125f : -1e30f;
        }

        // Online softmax: rows g (c0,c1) and g+8 (c2,c3); reduce across 4 lanes
        float m0 = -INFINITY, m1 = -INFINITY;
#pragma unroll
        for (int nt = 0; nt < 8; nt++) {
            m0 = fmaxf(m0, fmaxf(s[nt][0], s[nt][1]));
            m1 = fmaxf(m1, fmaxf(s[nt][2], s[nt][3]));
        }
#pragma unroll
        for (int off = 1; off <= 2; off <<= 1) {
            m0 = fmaxf(m0, __shfl_xor_sync(0xffffffffu, m0, off));
            m1 = fmaxf(m1, __shfl_xor_sync(0xffffffffu, m1, off));
        }
        float mn0 = fmaxf(mr0, m0), mn1 = fmaxf(mr1, m1);
        float al0 = __expf(mr0 - mn0), al1 = __expf(mr1 - mn1);
        float ls0 = 0.f, ls1 = 0.f;
#pragma unroll
        for (int nt = 0; nt < 8; nt++) {
            s[nt][0] = __expf(s[nt][0] - mn0);
            s[nt][1] = __expf(s[nt][1] - mn0);
            s[nt][2] = __expf(s[nt][2] - mn1);
            s[nt][3] = __expf(s[nt][3] - mn1);
            ls0 += s[nt][0] + s[nt][1];
            ls1 += s[nt][2] + s[nt][3];
        }
#pragma unroll
        for (int off = 1; off <= 2; off <<= 1) {
            ls0 += __shfl_xor_sync(0xffffffffu, ls0, off);
            ls1 += __shfl_xor_sync(0xffffffffu, ls1, off);
        }
        mr0 = mn0; mr1 = mn1;
        lr0 = lr0 * al0 + ls0;
        lr1 = lr1 * al1 + ls1;
#pragma unroll
        for (int nt = 0; nt < 8; nt++) {
            o[nt][0] *= al0; o[nt][1] *= al0;
            o[nt][2] *= al1; o[nt][3] *= al1;
        }
        // Store P (tf32-rounded) to smem
#pragma unroll
        for (int nt = 0; nt < 8; nt++) {
            *(float2*)&Ss[(qw + g) * ALD + nt * 8 + 2 * t4] =
                make_float2(f2tf(s[nt][0]), f2tf(s[nt][1]));
            *(float2*)&Ss[(qw + g + 8) * ALD + nt * 8 + 2 * t4] =
                make_float2(f2tf(s[nt][2]), f2tf(s[nt][3]));
        }
        __syncthreads();  // K reads + P writes complete

        // Load V tile (row-major [k][d], overwrites K)
        for (int e = tid; e < 64 * DD / 4; e += 128) {
            int r = e >> 4;
            int d = (e & 15) * 4;
            float4 v = *(const float4*)&g_V[base + (size_t)(k0 + r) * DD + d];
            float4 w = make_float4(f2tf(v.x), f2tf(v.y), f2tf(v.z), f2tf(v.w));
            *(float4*)&Ks[r * ALD + d] = w;
        }
        __syncthreads();

        // O += P @ V : 8 k-steps over KT=64
#pragma unroll
        for (int kk = 0; kk < 64; kk += 8) {
            uint32_t a0 = __float_as_uint(Ss[(qw + g) * ALD + kk + t4]);
            uint32_t a1 = __float_as_uint(Ss[(qw + g + 8) * ALD + kk + t4]);
            uint32_t a2 = __float_as_uint(Ss[(qw + g) * ALD + kk + t4 + 4]);
            uint32_t a3 = __float_as_uint(Ss[(qw + g + 8) * ALD + kk + t4 + 4]);
#pragma unroll
            for (int nt = 0; nt < 8; nt++) {
                uint32_t b0 = __float_as_uint(Ks[(kk + t4) * ALD + nt * 8 + g]);
                uint32_t b1 = __float_as_uint(Ks[(kk + t4 + 4) * ALD + nt * 8 + g]);
                mma_tf32(o[nt][0], o[nt][1], o[nt][2], o[nt][3], a0, a1, a2, a3, b0, b1);
            }
        }
        __syncthreads();  // PV reads done before next K overwrite
    }

    // Epilogue: normalize, write [B,S,H*D]
    float inv0 = 1.f / lr0, inv1 = 1.f / lr1;
    int row0 = q0 + qw + g, row1 = row0 + 8;
#pragma unroll
    for (int nt = 0; nt < 8; nt++) {
        int col = h * DD + nt * 8 + 2 * t4;
        *(float2*)&g_attn[((size_t)b * SSEQ + row0) * EE + col] =
            make_float2(o[nt][0] * inv0, o[nt][1] * inv0);
        *(float2*)&g_attn[((size_t)b * SSEQ + row1) * EE + col] =
            make_float2(o[nt][2] * inv1, o[nt][3] * inv1);
    }
}

// ---------------------------------------------------------------------------
extern "C" void kernel_launch(void* const* d_in, const int* in_sizes, int n_in,
                              void* d_out, int out_size) {
    const float* query = (const float*)d_in[0];
    const float* key   = (const float*)d_in[1];
    const float* value = (const float*)d_in[2];
    const int*   mask  = (const int*)d_in[3];
    const float* Wq = (const float*)d_in[4];
    const float* bq = (const float*)d_in[5];
    const float* Wk = (const float*)d_in[6];
    const float* bk = (const float*)d_in[7];
    const float* Wv = (const float*)d_in[8];
    const float* bv = (const float*)d_in[9];
    const float* Wo = (const float*)d_in[10];
    const float* bo = (const float*)d_in[11];
    float* out = (float*)d_out;

    dim3 gemm_grid(EE / 128, MMROWS / 128);  // (8, 32)

    gemm_tc<0><<<gemm_grid, 256>>>(query, Wq, bq, nullptr);
    gemm_tc<1><<<gemm_grid, 256>>>(key, Wk, bk, nullptr);
    gemm_tc<2><<<gemm_grid, 256>>>(value, Wv, bv, nullptr);

    const int NPAIR2 = 2 * BB * HH * SSEQ * 32;
    rope_kernel2<<<(NPAIR2 + 255) / 256, 256>>>();

    const int smem = 3 * 64 * ALD * (int)sizeof(float) + 64 * (int)sizeof(int);
    static bool attr_set = false;
    if (!attr_set) {
        cudaFuncSetAttribute(attn_tc, cudaFuncAttributeMaxDynamicSharedMemorySize, smem);
        attr_set = true;
    }
    attn_tc<<<dim3(SSEQ / 64, BB * HH), 128, smem>>>(mask);

    gemm_tc<3><<<gemm_grid, 256>>>(nullptr, Wo, bo, out);
}

// round 4
// speedup vs baseline: 3.2205x; 1.1375x over previous
#include <cuda_runtime.h>
#include <math.h>
#include <stdint.h>

// Problem dims
#define BB 2
#define SSEQ 2048
#define EE 1024
#define HH 16
#define DD 64
#define MMROWS (BB * SSEQ)  // 4096

// Scratch (device globals: allocation-free)
__device__ float g_Q[BB * HH * SSEQ * DD];
__device__ float g_K[BB * HH * SSEQ * DD];
__device__ float g_V[BB * HH * SSEQ * DD];
__device__ float g_attn[BB * SSEQ * EE];

// ---------------------------------------------------------------------------
// helpers
// ---------------------------------------------------------------------------
__device__ __forceinline__ float f2tf(float x) {
    uint32_t r;
    asm("cvt.rna.tf32.f32 %0, %1;" : "=r"(r) : "f"(x));
    return __uint_as_float(r);
}

__device__ __forceinline__ void mma_tf32(float& c0, float& c1, float& c2, float& c3,
                                         uint32_t a0, uint32_t a1, uint32_t a2, uint32_t a3,
                                         uint32_t b0, uint32_t b1) {
    asm volatile(
        "mma.sync.aligned.m16n8k8.row.col.f32.tf32.tf32.f32 "
        "{%0,%1,%2,%3}, {%4,%5,%6,%7}, {%8,%9}, {%0,%1,%2,%3};\n"
        : "+f"(c0), "+f"(c1), "+f"(c2), "+f"(c3)
        : "r"(a0), "r"(a1), "r"(a2), "r"(a3), "r"(b0), "r"(b1));
}

__device__ __forceinline__ void cpa16(uint32_t dst, const void* src) {
    asm volatile("cp.async.cg.shared.global [%0], [%1], 16;\n" :: "r"(dst), "l"(src));
}
__device__ __forceinline__ void cpa_commit() {
    asm volatile("cp.async.commit_group;\n");
}
__device__ __forceinline__ void cpa_wait_all() {
    asm volatile("cp.async.wait_group 0;\n");
}

// ---------------------------------------------------------------------------
// tf32 GEMM with register double-buffered smem: C = A @ W^T + bias
// Row-major smem tiles [128][20] (pad 4). 256 thr = 8 warps (2m x 4n).
// MODE 0/1/2 -> g_Q/g_K/g_V scatter (MODE2 stores tf32-rounded V);
// MODE 3 -> row-major Cout.
// ---------------------------------------------------------------------------
#define GPD 20

template <int MODE>
__global__ __launch_bounds__(256) void gemm_tc(const float* __restrict__ Ain,
                                               const float* __restrict__ W,
                                               const float* __restrict__ bias,
                                               float* __restrict__ Cout) {
    const float* A = (MODE == 3) ? g_attn : Ain;

    __shared__ __align__(16) float As[2][128][GPD];
    __shared__ __align__(16) float Bs[2][128][GPD];

    const int tid = threadIdx.x;
    const int n0 = blockIdx.x * 128;
    const int m0 = blockIdx.y * 128;
    const int wid = tid >> 5;
    const int lane = tid & 31;
    const int g = lane >> 2;
    const int t4 = lane & 3;
    const int mw = (wid & 1) * 64;
    const int nw = (wid >> 1) * 32;

    // staging indices: thread handles (m, kq) and (m+64, kq)
    const int sm = tid >> 2;          // 0..63
    const int skq = (tid & 3) * 4;    // 0,4,8,12

    float acc[4][4][4];
#pragma unroll
    for (int mt = 0; mt < 4; mt++)
#pragma unroll
        for (int nt = 0; nt < 4; nt++)
#pragma unroll
            for (int q = 0; q < 4; q++) acc[mt][nt][q] = 0.f;

    const int nsteps = EE / 16;  // 64

    // prologue: load tile 0 into stage 0
    {
        float4 va0 = *(const float4*)&A[(size_t)(m0 + sm) * EE + skq];
        float4 va1 = *(const float4*)&A[(size_t)(m0 + sm + 64) * EE + skq];
        float4 vw0 = *(const float4*)&W[(size_t)(n0 + sm) * EE + skq];
        float4 vw1 = *(const float4*)&W[(size_t)(n0 + sm + 64) * EE + skq];
        *(float4*)&As[0][sm][skq]      = make_float4(f2tf(va0.x), f2tf(va0.y), f2tf(va0.z), f2tf(va0.w));
        *(float4*)&As[0][sm + 64][skq] = make_float4(f2tf(va1.x), f2tf(va1.y), f2tf(va1.z), f2tf(va1.w));
        *(float4*)&Bs[0][sm][skq]      = make_float4(f2tf(vw0.x), f2tf(vw0.y), f2tf(vw0.z), f2tf(vw0.w));
        *(float4*)&Bs[0][sm + 64][skq] = make_float4(f2tf(vw1.x), f2tf(vw1.y), f2tf(vw1.z), f2tf(vw1.w));
    }
    __syncthreads();

    for (int s = 0; s < nsteps; s++) {
        const int cur = s & 1;
        float4 va0, va1, vw0, vw1;
        const bool more = (s + 1 < nsteps);
        if (more) {
            int k0 = (s + 1) * 16;
            va0 = *(const float4*)&A[(size_t)(m0 + sm) * EE + k0 + skq];
            va1 = *(const float4*)&A[(size_t)(m0 + sm + 64) * EE + k0 + skq];
            vw0 = *(const float4*)&W[(size_t)(n0 + sm) * EE + k0 + skq];
            vw1 = *(const float4*)&W[(size_t)(n0 + sm + 64) * EE + k0 + skq];
        }

#pragma unroll
        for (int kk = 0; kk < 16; kk += 8) {
            uint32_t af[4][4];
#pragma unroll
            for (int mt = 0; mt < 4; mt++) {
                int m = mw + mt * 16 + g;
                af[mt][0] = __float_as_uint(As[cur][m][kk + t4]);
                af[mt][1] = __float_as_uint(As[cur][m + 8][kk + t4]);
                af[mt][2] = __float_as_uint(As[cur][m][kk + t4 + 4]);
                af[mt][3] = __float_as_uint(As[cur][m + 8][kk + t4 + 4]);
            }
            uint32_t bf[4][2];
#pragma unroll
            for (int nt = 0; nt < 4; nt++) {
                int n = nw + nt * 8 + g;
                bf[nt][0] = __float_as_uint(Bs[cur][n][kk + t4]);
                bf[nt][1] = __float_as_uint(Bs[cur][n][kk + t4 + 4]);
            }
#pragma unroll
            for (int mt = 0; mt < 4; mt++)
#pragma unroll
                for (int nt = 0; nt < 4; nt++)
                    mma_tf32(acc[mt][nt][0], acc[mt][nt][1], acc[mt][nt][2], acc[mt][nt][3],
                             af[mt][0], af[mt][1], af[mt][2], af[mt][3],
                             bf[nt][0], bf[nt][1]);
        }

        if (more) {
            const int nxt = cur ^ 1;
            *(float4*)&As[nxt][sm][skq]      = make_float4(f2tf(va0.x), f2tf(va0.y), f2tf(va0.z), f2tf(va0.w));
            *(float4*)&As[nxt][sm + 64][skq] = make_float4(f2tf(va1.x), f2tf(va1.y), f2tf(va1.z), f2tf(va1.w));
            *(float4*)&Bs[nxt][sm][skq]      = make_float4(f2tf(vw0.x), f2tf(vw0.y), f2tf(vw0.z), f2tf(vw0.w));
            *(float4*)&Bs[nxt][sm + 64][skq] = make_float4(f2tf(vw1.x), f2tf(vw1.y), f2tf(vw1.z), f2tf(vw1.w));
            __syncthreads();
        }
    }

    // Epilogue: c0=(r,c) c1=(r,c+1) c2=(r+8,c) c3=(r+8,c+1); r=mw+mt*16+g, c=nw+nt*8+2t4
#pragma unroll
    for (int mt = 0; mt < 4; mt++) {
        int gm0 = m0 + mw + mt * 16 + g;
        int gm1 = gm0 + 8;
#pragma unroll
        for (int nt = 0; nt < 4; nt++) {
            int gn = n0 + nw + nt * 8 + 2 * t4;
            float bv0 = bias[gn], bv1 = bias[gn + 1];
            float e00 = acc[mt][nt][0] + bv0, e01 = acc[mt][nt][1] + bv1;
            float e10 = acc[mt][nt][2] + bv0, e11 = acc[mt][nt][3] + bv1;
            if (MODE == 2) {  // V consumed by cp.async path: round at producer
                e00 = f2tf(e00); e01 = f2tf(e01); e10 = f2tf(e10); e11 = f2tf(e11);
            }
            if (MODE < 3) {
                float* dst = (MODE == 0) ? g_Q : (MODE == 1) ? g_K : g_V;
                int h = gn >> 6, d = gn & 63;
                {
                    int bb = gm0 >> 11, ss = gm0 & (SSEQ - 1);
                    *(float2*)&dst[(((size_t)(bb * HH + h)) * SSEQ + ss) * DD + d] = make_float2(e00, e01);
                }
                {
                    int bb = gm1 >> 11, ss = gm1 & (SSEQ - 1);
                    *(float2*)&dst[(((size_t)(bb * HH + h)) * SSEQ + ss) * DD + d] = make_float2(e10, e11);
                }
            } else {
                *(float2*)&Cout[(size_t)gm0 * EE + gn] = make_float2(e00, e01);
                *(float2*)&Cout[(size_t)gm1 * EE + gn] = make_float2(e10, e11);
            }
        }
    }
}

// ---------------------------------------------------------------------------
// RoPE: now stores tf32-rounded Q,K (producer-side rounding; same values the
// attention kernel previously produced by rounding at load).
// ---------------------------------------------------------------------------
__global__ __launch_bounds__(256) void rope_kernel2() {
    __shared__ float invf[32];
    if (threadIdx.x < 32)
        invf[threadIdx.x] = (float)exp(-(double)threadIdx.x * (9.210340371976184 / 32.0));
    __syncthreads();

    const int NPAIR = BB * HH * SSEQ * 32;
    int idx = blockIdx.x * blockDim.x + threadIdx.x;
    if (idx >= 2 * NPAIR) return;
    float* buf = (idx < NPAIR) ? g_Q : g_K;
    int t = (idx < NPAIR) ? idx : idx - NPAIR;
    int p = t & 31;
    int s = (t >> 5) & (SSEQ - 1);

    float ang0 = (float)s * invf[(2 * p) & 31];
    float ang1 = (float)s * invf[(2 * p + 1) & 31];
    float s0, c0, s1, c1;
    sincosf(ang0, &s0, &c0);
    sincosf(ang1, &s1, &c1);

    float2* ptr = (float2*)buf + t;
    float2 x = *ptr;
    float2 y;
    y.x = f2tf(x.x * c0 - x.y * s0);
    y.y = f2tf(x.y * c1 + x.x * s1);
    *ptr = y;
}

// ---------------------------------------------------------------------------
// Flash attention, tf32 mma, cp.async double-buffered K/V, Q frags in regs.
// CTA = 128 thr (4 warps x 16 q-rows), K tile 64. smem stride 68.
// ---------------------------------------------------------------------------
#define ALD 68
#define NTILE (SSEQ / 64)  // 32

__global__ __launch_bounds__(128) void attn_tc(const int* __restrict__ mask) {
    extern __shared__ __align__(16) float sm[];
    float* Kb[2] = {sm, sm + 64 * ALD};
    float* Vb[2] = {sm + 2 * 64 * ALD, sm + 3 * 64 * ALD};
    float* Ss = sm + 4 * 64 * ALD;
    int* msk = (int*)(sm + 5 * 64 * ALD);  // [2][64]

    const int tid = threadIdx.x;
    const int wid = tid >> 5;
    const int lane = tid & 31;
    const int g = lane >> 2;
    const int t4 = lane & 3;
    const int qw = wid * 16;

    const int bh = blockIdx.y;
    const int q0 = blockIdx.x * 64;
    const int b = bh / HH;
    const int h = bh - b * HH;
    const size_t base = (size_t)bh * SSEQ * DD;

    const uint32_t smem_u32 = (uint32_t)__cvta_generic_to_shared(sm);
    const uint32_t kb_u32[2] = {smem_u32, smem_u32 + 64 * ALD * 4};
    const uint32_t vb_u32[2] = {smem_u32 + 2 * 64 * ALD * 4, smem_u32 + 3 * 64 * ALD * 4};
    const uint32_t msk_u32 = smem_u32 + 5 * 64 * ALD * 4;

    // Q fragments (loop-invariant): rows qw+g, qw+g+8 (already tf32-rounded)
    uint32_t aq[8][4];
    {
        const float* qr0 = &g_Q[base + (size_t)(q0 + qw + g) * DD];
        const float* qr1 = qr0 + 8 * DD;
#pragma unroll
        for (int kk8 = 0; kk8 < 8; kk8++) {
            aq[kk8][0] = __float_as_uint(qr0[kk8 * 8 + t4]);
            aq[kk8][1] = __float_as_uint(qr1[kk8 * 8 + t4]);
            aq[kk8][2] = __float_as_uint(qr0[kk8 * 8 + t4 + 4]);
            aq[kk8][3] = __float_as_uint(qr1[kk8 * 8 + t4 + 4]);
        }
    }

    float o[8][4];
#pragma unroll
    for (int nt = 0; nt < 8; nt++)
#pragma unroll
        for (int q = 0; q < 4; q++) o[nt][q] = 0.f;
    float mr0 = -INFINITY, mr1 = -INFINITY, lr0 = 0.f, lr1 = 0.f;

    // prefetch tile 0 into buffer 0
    {
        const int k0 = 0;
#pragma unroll
        for (int u = 0; u < 8; u++) {
            int n = tid + 128 * u;
            int r = n >> 4, c = (n & 15) * 4;
            cpa16(kb_u32[0] + (r * ALD + c) * 4, &g_K[base + (size_t)(k0 + r) * DD + c]);
            cpa16(vb_u32[0] + (r * ALD + c) * 4, &g_V[base + (size_t)(k0 + r) * DD + c]);
        }
        if (tid < 16) cpa16(msk_u32 + tid * 16, &mask[b * SSEQ + k0 + tid * 4]);
        cpa_commit();
    }

    for (int kt = 0; kt < NTILE; kt++) {
        cpa_wait_all();
        __syncthreads();

        const int cur = kt & 1;
        if (kt + 1 < NTILE) {
            const int k0 = (kt + 1) * 64;
            const int nb = cur ^ 1;
#pragma unroll
            for (int u = 0; u < 8; u++) {
                int n = tid + 128 * u;
                int r = n >> 4, c = (n & 15) * 4;
                cpa16(kb_u32[nb] + (r * ALD + c) * 4, &g_K[base + (size_t)(k0 + r) * DD + c]);
                cpa16(vb_u32[nb] + (r * ALD + c) * 4, &g_V[base + (size_t)(k0 + r) * DD + c]);
            }
            if (tid < 16) cpa16(msk_u32 + 256 * nb + tid * 16, &mask[b * SSEQ + k0 + tid * 4]);
            cpa_commit();
        }

        const float* Kc = Kb[cur];
        const float* Vc = Vb[cur];
        const int* mc = msk + 64 * cur;

        // S = Q @ K^T
        float s[8][4];
#pragma unroll
        for (int nt = 0; nt < 8; nt++)
#pragma unroll
            for (int q = 0; q < 4; q++) s[nt][q] = 0.f;
#pragma unroll
        for (int kk8 = 0; kk8 < 8; kk8++) {
            int kk = kk8 * 8;
#pragma unroll
            for (int nt = 0; nt < 8; nt++) {
                uint32_t b0 = __float_as_uint(Kc[(nt * 8 + g) * ALD + kk + t4]);
                uint32_t b1 = __float_as_uint(Kc[(nt * 8 + g) * ALD + kk + t4 + 4]);
                mma_tf32(s[nt][0], s[nt][1], s[nt][2], s[nt][3],
                         aq[kk8][0], aq[kk8][1], aq[kk8][2], aq[kk8][3], b0, b1);
            }
        }

        // scale + mask
#pragma unroll
        for (int nt = 0; nt < 8; nt++) {
            int mka = mc[nt * 8 + 2 * t4];
            int mkb = mc[nt * 8 + 2 * t4 + 1];
            s[nt][0] = mka ? s[nt][0] * 0.125f : -1e30f;
            s[nt][1] = mkb ? s[nt][1] * 0.125f : -1e30f;
            s[nt][2] = mka ? s[nt][2] * 0.125f : -1e30f;
            s[nt][3] = mkb ? s[nt][3] * 0.125f : -1e30f;
        }

        // online softmax (rows g / g+8; reduce over 4-lane group)
        float m0 = -INFINITY, m1 = -INFINITY;
#pragma unroll
        for (int nt = 0; nt < 8; nt++) {
            m0 = fmaxf(m0, fmaxf(s[nt][0], s[nt][1]));
            m1 = fmaxf(m1, fmaxf(s[nt][2], s[nt][3]));
        }
#pragma unroll
        for (int off = 1; off <= 2; off <<= 1) {
            m0 = fmaxf(m0, __shfl_xor_sync(0xffffffffu, m0, off));
            m1 = fmaxf(m1, __shfl_xor_sync(0xffffffffu, m1, off));
        }
        float mn0 = fmaxf(mr0, m0), mn1 = fmaxf(mr1, m1);
        float al0 = __expf(mr0 - mn0), al1 = __expf(mr1 - mn1);
        float ls0 = 0.f, ls1 = 0.f;
#pragma unroll
        for (int nt = 0; nt < 8; nt++) {
            s[nt][0] = __expf(s[nt][0] - mn0);
            s[nt][1] = __expf(s[nt][1] - mn0);
            s[nt][2] = __expf(s[nt][2] - mn1);
            s[nt][3] = __expf(s[nt][3] - mn1);
            ls0 += s[nt][0] + s[nt][1];
            ls1 += s[nt][2] + s[nt][3];
        }
#pragma unroll
        for (int off = 1; off <= 2; off <<= 1) {
            ls0 += __shfl_xor_sync(0xffffffffu, ls0, off);
            ls1 += __shfl_xor_sync(0xffffffffu, ls1, off);
        }
        mr0 = mn0; mr1 = mn1;
        lr0 = lr0 * al0 + ls0;
        lr1 = lr1 * al1 + ls1;
#pragma unroll
        for (int nt = 0; nt < 8; nt++) {
            o[nt][0] *= al0; o[nt][1] *= al0;
            o[nt][2] *= al1; o[nt][3] *= al1;
        }
        // P -> smem (tf32-rounded)
#pragma unroll
        for (int nt = 0; nt < 8; nt++) {
            *(float2*)&Ss[(qw + g) * ALD + nt * 8 + 2 * t4] =
                make_float2(f2tf(s[nt][0]), f2tf(s[nt][1]));
            *(float2*)&Ss[(qw + g + 8) * ALD + nt * 8 + 2 * t4] =
                make_float2(f2tf(s[nt][2]), f2tf(s[nt][3]));
        }
        __syncthreads();

        // O += P @ V
#pragma unroll
        for (int kk8 = 0; kk8 < 8; kk8++) {
            int kk = kk8 * 8;
            uint32_t a0 = __float_as_uint(Ss[(qw + g) * ALD + kk + t4]);
            uint32_t a1 = __float_as_uint(Ss[(qw + g + 8) * ALD + kk + t4]);
            uint32_t a2 = __float_as_uint(Ss[(qw + g) * ALD + kk + t4 + 4]);
            uint32_t a3 = __float_as_uint(Ss[(qw + g + 8) * ALD + kk + t4 + 4]);
#pragma unroll
            for (int nt = 0; nt < 8; nt++) {
                uint32_t b0 = __float_as_uint(Vc[(kk + t4) * ALD + nt * 8 + g]);
                uint32_t b1 = __float_as_uint(Vc[(kk + t4 + 4) * ALD + nt * 8 + g]);
                mma_tf32(o[nt][0], o[nt][1], o[nt][2], o[nt][3], a0, a1, a2, a3, b0, b1);
            }
        }
    }

    // epilogue
    float inv0 = 1.f / lr0, inv1 = 1.f / lr1;
    int row0 = q0 + qw + g, row1 = row0 + 8;
#pragma unroll
    for (int nt = 0; nt < 8; nt++) {
        int col = h * DD + nt * 8 + 2 * t4;
        *(float2*)&g_attn[((size_t)b * SSEQ + row0) * EE + col] =
            make_float2(o[nt][0] * inv0, o[nt][1] * inv0);
        *(float2*)&g_attn[((size_t)b * SSEQ + row1) * EE + col] =
            make_float2(o[nt][2] * inv1, o[nt][3] * inv1);
    }
}

// ---------------------------------------------------------------------------
extern "C" void kernel_launch(void* const* d_in, const int* in_sizes, int n_in,
                              void* d_out, int out_size) {
    const float* query = (const float*)d_in[0];
    const float* key   = (const float*)d_in[1];
    const float* value = (const float*)d_in[2];
    const int*   mask  = (const int*)d_in[3];
    const float* Wq = (const float*)d_in[4];
    const float* bq = (const float*)d_in[5];
    const float* Wk = (const float*)d_in[6];
    const float* bk = (const float*)d_in[7];
    const float* Wv = (const float*)d_in[8];
    const float* bv = (const float*)d_in[9];
    const float* Wo = (const float*)d_in[10];
    const float* bo = (const float*)d_in[11];
    float* out = (float*)d_out;

    dim3 gemm_grid(EE / 128, MMROWS / 128);  // (8, 32)

    gemm_tc<0><<<gemm_grid, 256>>>(query, Wq, bq, nullptr);
    gemm_tc<1><<<gemm_grid, 256>>>(key, Wk, bk, nullptr);
    gemm_tc<2><<<gemm_grid, 256>>>(value, Wv, bv, nullptr);

    const int NPAIR2 = 2 * BB * HH * SSEQ * 32;
    rope_kernel2<<<(NPAIR2 + 255) / 256, 256>>>();

    const int smem = 5 * 64 * ALD * (int)sizeof(float) + 2 * 64 * (int)sizeof(int);
    static bool attr_set = false;
    if (!attr_set) {
        cudaFuncSetAttribute(attn_tc, cudaFuncAttributeMaxDynamicSharedMemorySize, smem);
        attr_set = true;
    }
    attn_tc<<<dim3(SSEQ / 64, BB * HH), 128, smem>>>(mask);

    gemm_tc<3><<<gemm_grid, 256>>>(nullptr, Wo, bo, out);
}